// round 9
// baseline (speedup 1.0000x reference)
#include <cuda_runtime.h>
#include <cuda_bf16.h>

#define N_NODES 100000
#define B_DIM   16
#define GRID    444           // 3 blocks/SM x 148 SMs — all resident (barrier-safe)
#define NTHR    256
#define TOTAL_THREADS (GRID * NTHR)

// Scratch: transposed x and accumulator, [N, B] layout so one edge's 16
// batch lanes are 64 contiguous bytes.
__device__ float g_xt[N_NODES * B_DIM];
__device__ float g_yt[N_NODES * B_DIM];
// Monotonic barrier counter: +1/block at barrier1, barrier2, exit (3*GRID
// total per launch); last exit arrival resets to 0 for the next graph replay.
__device__ unsigned g_ctr;

// Grid-wide barrier. All GRID blocks are resident (launch_bounds enforces
// occupancy >= 3/SM: regs<=64, smem 16.6KB), so spinning cannot deadlock.
// Counter is monotonic within a launch; targets grow (GRID, 2*GRID).
__device__ __forceinline__ void grid_barrier(unsigned target) {
    __threadfence();          // flush this thread's global writes
    __syncthreads();          // all threads in block done + fenced
    if (threadIdx.x == 0) {
        atomicAdd(&g_ctr, 1u);
        while (*(volatile unsigned*)&g_ctr < target) { __nanosleep(64); }
    }
    __syncthreads();
    __threadfence();
}

// ---------------------------------------------------------------------------
// Phase T: transpose one 256-node tile of x [B,N] -> g_xt [N,B], zero g_yt.
// (R6 proven body.)
// ---------------------------------------------------------------------------
__device__ __forceinline__ void do_transpose_tile(
    float (*tile)[260], const float* __restrict__ x, int N, int tile_idx) {
    const int n0 = tile_idx * 256;
    const int tid = threadIdx.x;
    const int N4 = N >> 2;

    float4 v[4];
    #pragma unroll
    for (int p = 0; p < 4; p++) {
        int idx = p * 256 + tid;
        int b  = idx >> 6;
        int nq = idx & 63;
        int gq = (n0 >> 2) + nq;
        v[p] = make_float4(0.f, 0.f, 0.f, 0.f);
        if (gq < N4) v[p] = ((const float4*)x)[b * N4 + gq];
    }
    #pragma unroll
    for (int p = 0; p < 4; p++) {
        int idx = p * 256 + tid;
        int b  = idx >> 6;
        int nq = idx & 63;
        tile[b][4 * nq + 0] = v[p].x;
        tile[b][4 * nq + 1] = v[p].y;
        tile[b][4 * nq + 2] = v[p].z;
        tile[b][4 * nq + 3] = v[p].w;
    }
    __syncthreads();

    #pragma unroll
    for (int p = 0; p < 4; p++) {
        int t = p * 256 + tid;
        int n = t >> 2;
        int q = t & 3;
        int nn = n0 + n;
        if (nn < N) {
            float4 w;
            w.x = tile[4 * q + 0][n];
            w.y = tile[4 * q + 1][n];
            w.z = tile[4 * q + 2][n];
            w.w = tile[4 * q + 3][n];
            *(float4*)&g_xt[nn * B_DIM + 4 * q] = w;
            *(float4*)&g_yt[nn * B_DIM + 4 * q] = make_float4(0.f, 0.f, 0.f, 0.f);
        }
    }
    __syncthreads();   // tile smem reused by phase N later
}

// One edge task (edge, batch-quad): proven R2/R7 body.
__device__ __forceinline__ void do_edge_task(
    const int* __restrict__ src_idx, const int* __restrict__ dst_idx,
    const float* __restrict__ edge_alpha, const float* __restrict__ edge_w,
    const float* __restrict__ edge_b, int t) {
    int e = t >> 2;
    int q = t & 3;
    int   s  = __ldg(&src_idx[e]);
    int   d  = __ldg(&dst_idx[e]);
    float w  = __ldg(&edge_w[e]);
    float bb = __ldg(&edge_b[e]);
    float a  = __ldg(&edge_alpha[e]);

    float4 xv = __ldg((const float4*)&g_xt[s * B_DIM + 4 * q]);

    float l0 = fmaf(w, xv.x, bb);
    float l1 = fmaf(w, xv.y, bb);
    float l2 = fmaf(w, xv.z, bb);
    float l3 = fmaf(w, xv.w, bb);
    float h0, h1, h2, h3;
    asm("tanh.approx.f32 %0, %1;" : "=f"(h0) : "f"(l0));
    asm("tanh.approx.f32 %0, %1;" : "=f"(h1) : "f"(l1));
    asm("tanh.approx.f32 %0, %1;" : "=f"(h2) : "f"(l2));
    asm("tanh.approx.f32 %0, %1;" : "=f"(h3) : "f"(l3));
    float m0 = fmaf(a, h0 - l0, l0);
    float m1 = fmaf(a, h1 - l1, l1);
    float m2 = fmaf(a, h2 - l2, l2);
    float m3 = fmaf(a, h3 - l3, l3);
    size_t gaddr = __cvta_generic_to_global(&g_yt[d * B_DIM + 4 * q]);
    asm volatile("red.global.add.v4.f32 [%0], {%1, %2, %3, %4};"
                 :: "l"(gaddr), "f"(m0), "f"(m1), "f"(m2), "f"(m3)
                 : "memory");
}

// ---------------------------------------------------------------------------
// Phase N: node stage + transpose back for one 256-node tile. (R6 body.)
// ---------------------------------------------------------------------------
__device__ __forceinline__ void do_node_tile(
    float (*tile)[260],
    const float* __restrict__ node_alpha, const float* __restrict__ node_w,
    const float* __restrict__ node_b, float* __restrict__ out,
    int N, int tile_idx) {
    const int n0 = tile_idx * 256;
    const int tid = threadIdx.x;
    const int N4 = N >> 2;

    float4 v[4];
    #pragma unroll
    for (int p = 0; p < 4; p++) {
        int t = p * 256 + tid;
        int n = t >> 2;
        int q = t & 3;
        int nn = n0 + n;
        v[p] = make_float4(0.f, 0.f, 0.f, 0.f);
        if (nn < N) v[p] = *(const float4*)&g_yt[nn * B_DIM + 4 * q];
    }
    #pragma unroll
    for (int p = 0; p < 4; p++) {
        int t = p * 256 + tid;
        int n = t >> 2;
        int q = t & 3;
        tile[4 * q + 0][n] = v[p].x;
        tile[4 * q + 1][n] = v[p].y;
        tile[4 * q + 2][n] = v[p].z;
        tile[4 * q + 3][n] = v[p].w;
    }
    __syncthreads();

    #pragma unroll
    for (int p = 0; p < 4; p++) {
        int idx = p * 256 + tid;
        int b  = idx >> 6;
        int nq = idx & 63;
        int gq = (n0 >> 2) + nq;
        if (gq < N4) {
            float4 r;
            #pragma unroll
            for (int k = 0; k < 4; k++) {
                int nl = 4 * nq + k;
                int ng = n0 + nl;
                float y   = tile[b][nl];
                float ww  = node_w[ng];
                float bb  = node_b[ng];
                float aa  = node_alpha[ng];
                float lin = fmaf(ww, y, bb);
                float th;
                asm("tanh.approx.f32 %0, %1;" : "=f"(th) : "f"(lin));
                ((float*)&r)[k] = fmaf(aa, th - lin, lin);
            }
            ((float4*)out)[b * N4 + gq] = r;
        }
    }
    __syncthreads();
}

// ---------------------------------------------------------------------------
// Fused persistent kernel: T -> barrier -> E -> barrier -> N.
// ---------------------------------------------------------------------------
__global__ void __launch_bounds__(NTHR, 3)
fused_kernel(const float* __restrict__ x,
             const int*   __restrict__ src_idx,
             const int*   __restrict__ dst_idx,
             const float* __restrict__ edge_alpha,
             const float* __restrict__ edge_w,
             const float* __restrict__ edge_b,
             const float* __restrict__ node_alpha,
             const float* __restrict__ node_w,
             const float* __restrict__ node_b,
             float* __restrict__ out,
             int E, int N) {
    __shared__ float tile[16][260];
    const int bid = blockIdx.x;
    const int n_tiles = (N + 255) / 256;

    // ---- Phase T ----
    for (int ti = bid; ti < n_tiles; ti += GRID)
        do_transpose_tile(tile, x, N, ti);

    grid_barrier(GRID);

    // ---- Phase E: grid-stride pairs (2-task ILP, proven in R7) ----
    {
        const int T = E * 4;
        const int gtid = bid * NTHR + threadIdx.x;
        for (int t0 = gtid; t0 < T; t0 += 2 * TOTAL_THREADS) {
            int t1 = t0 + TOTAL_THREADS;
            if (t1 < T) {
                // interleave: both param+gather chains in flight
                do_edge_task(src_idx, dst_idx, edge_alpha, edge_w, edge_b, t0);
                do_edge_task(src_idx, dst_idx, edge_alpha, edge_w, edge_b, t1);
            } else {
                do_edge_task(src_idx, dst_idx, edge_alpha, edge_w, edge_b, t0);
            }
        }
    }

    grid_barrier(2 * GRID);

    // ---- Phase N ----
    for (int ti = bid; ti < n_tiles; ti += GRID)
        do_node_tile(tile, node_alpha, node_w, node_b, out, N, ti);

    // ---- Exit: last arrival resets counter for next graph replay ----
    __syncthreads();
    if (threadIdx.x == 0) {
        __threadfence();
        unsigned old = atomicAdd(&g_ctr, 1u);
        if (old == 3u * GRID - 1u) g_ctr = 0u;   // all blocks past barrier 2
    }
}

// ---------------------------------------------------------------------------
// Input order: x, src_idx, dst_idx, edge_alpha, edge_w, edge_b,
// node_alpha, node_w, node_b. Output: float32 [B, N].
// ---------------------------------------------------------------------------
extern "C" void kernel_launch(void* const* d_in, const int* in_sizes, int n_in,
                              void* d_out, int out_size) {
    const float* x          = (const float*)d_in[0];
    const int*   src_idx    = (const int*)  d_in[1];
    const int*   dst_idx    = (const int*)  d_in[2];
    const float* edge_alpha = (const float*)d_in[3];
    const float* edge_w     = (const float*)d_in[4];
    const float* edge_b     = (const float*)d_in[5];
    const float* node_alpha = (const float*)d_in[6];
    const float* node_w     = (const float*)d_in[7];
    const float* node_b     = (const float*)d_in[8];
    float* out = (float*)d_out;

    const int E = in_sizes[1];
    const int N = in_sizes[6];

    fused_kernel<<<GRID, NTHR>>>(x, src_idx, dst_idx, edge_alpha, edge_w,
                                 edge_b, node_alpha, node_w, node_b, out,
                                 E, N);
}

// round 10
// speedup vs baseline: 1.1317x; 1.1317x over previous
#include <cuda_runtime.h>
#include <cuda_bf16.h>

#define N_NODES 100000
#define B_DIM   16

// Scratch: transposed x and accumulator, [N, B] layout so one edge's 16
// batch lanes are 64 contiguous bytes.
__device__ float g_xt[N_NODES * B_DIM];
__device__ float g_yt[N_NODES * B_DIM];

#define PDL_LAUNCH_DEPENDENTS() asm volatile("griddepcontrol.launch_dependents;" ::: "memory")
#define PDL_WAIT()              asm volatile("griddepcontrol.wait;" ::: "memory")

// ---------------------------------------------------------------------------
// Kernel 1: transpose x [B,N] -> g_xt [N,B], and zero g_yt (zeroing HERE,
// right before the edge kernel's atomics — proven load-bearing R2 vs R4).
// Triggers dependent (edge) launch immediately so edge preambles overlap.
// ---------------------------------------------------------------------------
__global__ void __launch_bounds__(256)
transpose_zero_kernel(const float* __restrict__ x, int N) {
    PDL_LAUNCH_DEPENDENTS();   // edge blocks may start their param preamble now

    __shared__ float tile[16][260];
    const int n0 = blockIdx.x * 256;
    const int tid = threadIdx.x;
    const int N4 = N >> 2;

    float4 v[4];
    #pragma unroll
    for (int p = 0; p < 4; p++) {
        int idx = p * 256 + tid;
        int b  = idx >> 6;
        int nq = idx & 63;
        int gq = (n0 >> 2) + nq;
        v[p] = make_float4(0.f, 0.f, 0.f, 0.f);
        if (gq < N4) v[p] = ((const float4*)x)[b * N4 + gq];
    }
    #pragma unroll
    for (int p = 0; p < 4; p++) {
        int idx = p * 256 + tid;
        int b  = idx >> 6;
        int nq = idx & 63;
        tile[b][4 * nq + 0] = v[p].x;
        tile[b][4 * nq + 1] = v[p].y;
        tile[b][4 * nq + 2] = v[p].z;
        tile[b][4 * nq + 3] = v[p].w;
    }
    __syncthreads();

    #pragma unroll
    for (int p = 0; p < 4; p++) {
        int t = p * 256 + tid;
        int n = t >> 2;
        int q = t & 3;
        int nn = n0 + n;
        if (nn < N) {
            float4 w;
            w.x = tile[4 * q + 0][n];
            w.y = tile[4 * q + 1][n];
            w.z = tile[4 * q + 2][n];
            w.w = tile[4 * q + 3][n];
            *(float4*)&g_xt[nn * B_DIM + 4 * q] = w;
            *(float4*)&g_yt[nn * B_DIM + 4 * q] = make_float4(0.f, 0.f, 0.f, 0.f);
        }
    }
}

// ---------------------------------------------------------------------------
// Kernel 2: edge stage — R7's proven 2-task split-grid body, with PDL:
// param loads (independent of transpose output) issue BEFORE the wait,
// overlapping the transpose tail; gathers/REDs after the wait.
// ---------------------------------------------------------------------------
__global__ void __launch_bounds__(256)
edge_kernel(const int*   __restrict__ src_idx,
            const int*   __restrict__ dst_idx,
            const float* __restrict__ edge_alpha,
            const float* __restrict__ edge_w,
            const float* __restrict__ edge_b,
            int E, int half) {
    int t0 = blockIdx.x * blockDim.x + threadIdx.x;
    if (t0 >= half) return;
    int t1 = t0 + half;
    const int T = E * 4;
    bool has1 = (t1 < T);

    int eA = t0 >> 2, qA = t0 & 3;
    int eB = t1 >> 2, qB = t1 & 3;

    // ---- Preamble: param loads only (do NOT touch g_xt / g_yt) ----
    int   sA = __ldg(&src_idx[eA]);
    int   dA = __ldg(&dst_idx[eA]);
    float wA = __ldg(&edge_w[eA]);
    float bA = __ldg(&edge_b[eA]);
    float aA = __ldg(&edge_alpha[eA]);

    int eBs = has1 ? eB : eA;
    int   sB = __ldg(&src_idx[eBs]);
    int   dB = __ldg(&dst_idx[eBs]);
    float wB = __ldg(&edge_w[eBs]);
    float bB = __ldg(&edge_b[eBs]);
    float aB = __ldg(&edge_alpha[eBs]);

    PDL_LAUNCH_DEPENDENTS();   // let node kernel's preamble start
    PDL_WAIT();                // transpose complete + writes visible

    // ---- Two independent gathers in flight ----
    float4 xA = __ldg((const float4*)&g_xt[sA * B_DIM + 4 * qA]);
    float4 xB = __ldg((const float4*)&g_xt[sB * B_DIM + 4 * qB]);

    // Task A math + RED
    {
        float l0 = fmaf(wA, xA.x, bA);
        float l1 = fmaf(wA, xA.y, bA);
        float l2 = fmaf(wA, xA.z, bA);
        float l3 = fmaf(wA, xA.w, bA);
        float h0, h1, h2, h3;
        asm("tanh.approx.f32 %0, %1;" : "=f"(h0) : "f"(l0));
        asm("tanh.approx.f32 %0, %1;" : "=f"(h1) : "f"(l1));
        asm("tanh.approx.f32 %0, %1;" : "=f"(h2) : "f"(l2));
        asm("tanh.approx.f32 %0, %1;" : "=f"(h3) : "f"(l3));
        float m0 = fmaf(aA, h0 - l0, l0);
        float m1 = fmaf(aA, h1 - l1, l1);
        float m2 = fmaf(aA, h2 - l2, l2);
        float m3 = fmaf(aA, h3 - l3, l3);
        size_t gaddr = __cvta_generic_to_global(&g_yt[dA * B_DIM + 4 * qA]);
        asm volatile("red.global.add.v4.f32 [%0], {%1, %2, %3, %4};"
                     :: "l"(gaddr), "f"(m0), "f"(m1), "f"(m2), "f"(m3)
                     : "memory");
    }

    // Task B math + RED
    if (has1) {
        float l0 = fmaf(wB, xB.x, bB);
        float l1 = fmaf(wB, xB.y, bB);
        float l2 = fmaf(wB, xB.z, bB);
        float l3 = fmaf(wB, xB.w, bB);
        float h0, h1, h2, h3;
        asm("tanh.approx.f32 %0, %1;" : "=f"(h0) : "f"(l0));
        asm("tanh.approx.f32 %0, %1;" : "=f"(h1) : "f"(l1));
        asm("tanh.approx.f32 %0, %1;" : "=f"(h2) : "f"(l2));
        asm("tanh.approx.f32 %0, %1;" : "=f"(h3) : "f"(l3));
        float m0 = fmaf(aB, h0 - l0, l0);
        float m1 = fmaf(aB, h1 - l1, l1);
        float m2 = fmaf(aB, h2 - l2, l2);
        float m3 = fmaf(aB, h3 - l3, l3);
        size_t gaddr = __cvta_generic_to_global(&g_yt[dB * B_DIM + 4 * qB]);
        asm volatile("red.global.add.v4.f32 [%0], {%1, %2, %3, %4};"
                     :: "l"(gaddr), "f"(m0), "f"(m1), "f"(m2), "f"(m3)
                     : "memory");
    }
}

// ---------------------------------------------------------------------------
// Kernel 3: node stage + transpose back. PDL: per-node params staged into
// smem BEFORE the wait (independent of g_yt), body after.
// ---------------------------------------------------------------------------
__global__ void __launch_bounds__(256)
node_kernel(const float* __restrict__ node_alpha,
            const float* __restrict__ node_w,
            const float* __restrict__ node_b,
            float* __restrict__ out, int N) {
    __shared__ float tile[16][260];
    __shared__ float s_w[256], s_b[256], s_a[256];
    const int n0 = blockIdx.x * 256;
    const int tid = threadIdx.x;
    const int N4 = N >> 2;

    // ---- Preamble: node params for this tile (independent of edge) ----
    {
        int nn = n0 + tid;
        float w = 0.f, b = 0.f, a = 0.f;
        if (nn < N) {
            w = __ldg(&node_w[nn]);
            b = __ldg(&node_b[nn]);
            a = __ldg(&node_alpha[nn]);
        }
        s_w[tid] = w; s_b[tid] = b; s_a[tid] = a;
    }
    __syncthreads();

    PDL_WAIT();   // edge complete; all REDs to g_yt visible

    float4 v[4];
    #pragma unroll
    for (int p = 0; p < 4; p++) {
        int t = p * 256 + tid;
        int n = t >> 2;
        int q = t & 3;
        int nn = n0 + n;
        v[p] = make_float4(0.f, 0.f, 0.f, 0.f);
        if (nn < N) v[p] = *(const float4*)&g_yt[nn * B_DIM + 4 * q];
    }
    #pragma unroll
    for (int p = 0; p < 4; p++) {
        int t = p * 256 + tid;
        int n = t >> 2;
        int q = t & 3;
        tile[4 * q + 0][n] = v[p].x;
        tile[4 * q + 1][n] = v[p].y;
        tile[4 * q + 2][n] = v[p].z;
        tile[4 * q + 3][n] = v[p].w;
    }
    __syncthreads();

    #pragma unroll
    for (int p = 0; p < 4; p++) {
        int idx = p * 256 + tid;
        int b  = idx >> 6;
        int nq = idx & 63;
        int gq = (n0 >> 2) + nq;
        if (gq < N4) {
            float4 r;
            #pragma unroll
            for (int k = 0; k < 4; k++) {
                int nl = 4 * nq + k;
                float y   = tile[b][nl];
                float lin = fmaf(s_w[nl], y, s_b[nl]);
                float th;
                asm("tanh.approx.f32 %0, %1;" : "=f"(th) : "f"(lin));
                ((float*)&r)[k] = fmaf(s_a[nl], th - lin, lin);
            }
            ((float4*)out)[b * N4 + gq] = r;
        }
    }
}

// ---------------------------------------------------------------------------
// Input order: x, src_idx, dst_idx, edge_alpha, edge_w, edge_b,
// node_alpha, node_w, node_b. Output: float32 [B, N].
// ---------------------------------------------------------------------------
extern "C" void kernel_launch(void* const* d_in, const int* in_sizes, int n_in,
                              void* d_out, int out_size) {
    const float* x          = (const float*)d_in[0];
    const int*   src_idx    = (const int*)  d_in[1];
    const int*   dst_idx    = (const int*)  d_in[2];
    const float* edge_alpha = (const float*)d_in[3];
    const float* edge_w     = (const float*)d_in[4];
    const float* edge_b     = (const float*)d_in[5];
    const float* node_alpha = (const float*)d_in[6];
    const float* node_w     = (const float*)d_in[7];
    const float* node_b     = (const float*)d_in[8];
    float* out = (float*)d_out;

    const int E = in_sizes[1];
    const int N = in_sizes[6];

    const int n_tiles = (N + 255) / 256;

    // K1: plain launch.
    transpose_zero_kernel<<<n_tiles, 256>>>(x, N);

    cudaLaunchAttribute pdl_attr[1];
    pdl_attr[0].id = cudaLaunchAttributeProgrammaticStreamSerialization;
    pdl_attr[0].val.programmaticStreamSerializationAllowed = 1;

    // K2: edge, PDL-dependent on transpose.
    {
        const int T = E * 4;
        int half = ((T + 1) / 2 + 255) & ~255;
        cudaLaunchConfig_t cfg = {};
        cfg.gridDim  = dim3(half / 256, 1, 1);
        cfg.blockDim = dim3(256, 1, 1);
        cfg.dynamicSmemBytes = 0;
        cfg.stream = 0;
        cfg.attrs = pdl_attr;
        cfg.numAttrs = 1;
        cudaLaunchKernelEx(&cfg, edge_kernel, src_idx, dst_idx, edge_alpha,
                           edge_w, edge_b, E, half);
    }

    // K3: node, PDL-dependent on edge.
    {
        cudaLaunchConfig_t cfg = {};
        cfg.gridDim  = dim3(n_tiles, 1, 1);
        cfg.blockDim = dim3(256, 1, 1);
        cfg.dynamicSmemBytes = 0;
        cfg.stream = 0;
        cfg.attrs = pdl_attr;
        cfg.numAttrs = 1;
        cudaLaunchKernelEx(&cfg, node_kernel, node_alpha, node_w, node_b,
                           out, N);
    }
}